// round 5
// baseline (speedup 1.0000x reference)
#include <cuda_runtime.h>
#include <cstdint>

// BlockMaskGenerator: 4 random rectangles per batch -> 256 x 16384 bool
// target mask + complement context mask (bool promoted to f32 by harness).
//   d_out = [context_mask (256*16384 f32), target_mask (256*16384 f32)]
// 33.5 MB pure stores, L2-resident; LTS floor ~2.7us.
// R4 postmortem: issue 15.8%, nothing saturated -> latency/barrier/wave bound.
// R5: 1024 CTAs x 256 thr (single wave), no smem/no barrier (per-warp rect
// compute + shfl broadcast), 8 STG.128 per thread.

#define BM_BATCH   256
#define BM_NBLK    4
#define BM_H       128
#define BM_W       128
#define BM_SEQ     (BM_H * BM_W)

__global__ __launch_bounds__(256, 8)
void block_mask_kernel(const float* __restrict__ scales_u,
                       const float* __restrict__ rand_top,
                       const float* __restrict__ rand_left,
                       float* __restrict__ out)
{
    const int bid  = blockIdx.x;
    const int b    = bid >> 2;                  // batch
    const int tid  = threadIdx.x;
    const int lane = tid & 31;

    // Lanes 0..3 of every warp compute the 4 rects for this batch.
    int top = 0, bot = 0, left = 0, right = 0;
    if (lane < BM_NBLK) {
        const int i = b * BM_NBLK + lane;
        // scales = 0.15 + u*0.05 (separate mul/add, f32 rn — match JAX; no FMA)
        float scale = __fadd_rn(0.15f, __fmul_rn(scales_u[i], 0.05f));
        float areaf = __fmul_rn(__fmul_rn(scale, 128.0f), 128.0f); // pow2 exact
        int area = (int)areaf;                                     // trunc
        int h = (int)__fsqrt_rn(__fdiv_rn((float)area, 0.75f));
        h = min(max(h, 1), BM_H);
        int w = (int)__fdiv_rn((float)area, (float)h);
        w = min(max(w, 1), BM_W);
        int max_t = max(BM_H - h + 1, 1);
        int max_l = max(BM_W - w + 1, 1);
        top  = (int)__fmul_rn(rand_top[i],  (float)max_t);
        left = (int)__fmul_rn(rand_left[i], (float)max_l);
        bot   = top + h;
        right = left + w;
    }

    // Thread -> (row, 16-col segment): 32 rows per CTA, 8 segments of 16.
    const int row   = (bid & 3) * 32 + (tid >> 3);
    const int cbase = (tid & 7) * 16;

    // 16-bit column membership mask via shfl broadcast (no smem, no barrier)
    unsigned m = 0u;
#pragma unroll
    for (int j = 0; j < BM_NBLK; j++) {
        int tj = __shfl_sync(0xFFFFFFFFu, top,   j);
        int bj = __shfl_sync(0xFFFFFFFFu, bot,   j);
        int lj = __shfl_sync(0xFFFFFFFFu, left,  j);
        int rj = __shfl_sync(0xFFFFFFFFu, right, j);
        bool row_in = (row >= tj) & (row < bj);
        int lo = max(lj - cbase, 0);
        int hi = min(rj - cbase, 16);
        if (row_in && hi > lo) {
            m |= ((1u << hi) - 1u) & ~((1u << lo) - 1u);
        }
    }

    float* ctx = out;
    float* tgt = out + (size_t)BM_BATCH * BM_SEQ;
    const size_t off = (size_t)b * BM_SEQ + (size_t)row * BM_W + cbase;

    const unsigned ONE = 0x3F800000u;  // 1.0f

    uint4 t[4], c[4];
#pragma unroll
    for (int g = 0; g < 4; g++) {
        unsigned nib = (m >> (4 * g)) & 0xFu;
        t[g].x = (nib & 1u) ? ONE : 0u;
        t[g].y = (nib & 2u) ? ONE : 0u;
        t[g].z = (nib & 4u) ? ONE : 0u;
        t[g].w = (nib & 8u) ? ONE : 0u;
        c[g].x = t[g].x ^ ONE;
        c[g].y = t[g].y ^ ONE;
        c[g].z = t[g].z ^ ONE;
        c[g].w = t[g].w ^ ONE;
    }
#pragma unroll
    for (int g = 0; g < 4; g++)
        *reinterpret_cast<uint4*>(tgt + off + 4 * g) = t[g];
#pragma unroll
    for (int g = 0; g < 4; g++)
        *reinterpret_cast<uint4*>(ctx + off + 4 * g) = c[g];
}

extern "C" void kernel_launch(void* const* d_in, const int* in_sizes, int n_in,
                              void* d_out, int out_size)
{
    const float* scales_u  = (const float*)d_in[0];
    const float* rand_top  = (const float*)d_in[1];
    const float* rand_left = (const float*)d_in[2];
    float* out = (float*)d_out;

    block_mask_kernel<<<BM_BATCH * 4, 256>>>(scales_u, rand_top, rand_left, out);
}

// round 6
// speedup vs baseline: 1.4061x; 1.4061x over previous
#include <cuda_runtime.h>
#include <cstdint>

// BlockMaskGenerator: 4 random rectangles per batch -> 256 x 16384 bool
// target mask + complement context mask (bool promoted to f32 by harness).
//   d_out = [context_mask (256*16384 f32), target_mask (256*16384 f32)]
// 33.5 MB pure stores, L2-resident.
// R5 postmortem: stores were strided within each warp instruction (64B-stride
// 16B chunks -> 4x sector inflation, L1 pinned at 49%, 13.3us invariant).
// R6: warp owns whole rows; lane l covers cols [4l,4l+4) -> every STG.128 is
// one fully-coalesced 512B row write. 8 STG.128 per thread (4 rows x tgt+ctx).

#define BM_BATCH   256
#define BM_NBLK    4
#define BM_H       128
#define BM_W       128
#define BM_SEQ     (BM_H * BM_W)

__global__ __launch_bounds__(256, 8)
void block_mask_kernel(const float* __restrict__ scales_u,
                       const float* __restrict__ rand_top,
                       const float* __restrict__ rand_left,
                       float* __restrict__ out)
{
    const int bid  = blockIdx.x;
    const int b    = bid >> 2;                  // batch
    const int tid  = threadIdx.x;
    const int lane = tid & 31;
    const int warp = tid >> 5;

    // Lanes 0..3 of every warp compute the 4 rects for this batch.
    int top = 0, bot = 0, left = 0, right = 0;
    if (lane < BM_NBLK) {
        const int i = b * BM_NBLK + lane;
        // scales = 0.15 + u*0.05 (separate mul/add, f32 rn — match JAX; no FMA)
        float scale = __fadd_rn(0.15f, __fmul_rn(scales_u[i], 0.05f));
        float areaf = __fmul_rn(__fmul_rn(scale, 128.0f), 128.0f); // pow2 exact
        int area = (int)areaf;                                     // trunc
        int h = (int)__fsqrt_rn(__fdiv_rn((float)area, 0.75f));
        h = min(max(h, 1), BM_H);
        int w = (int)__fdiv_rn((float)area, (float)h);
        w = min(max(w, 1), BM_W);
        int max_t = max(BM_H - h + 1, 1);
        int max_l = max(BM_W - w + 1, 1);
        top  = (int)__fmul_rn(rand_top[i],  (float)max_t);
        left = (int)__fmul_rn(rand_left[i], (float)max_l);
        bot   = top + h;
        right = left + w;
    }

    // Warp owns 4 consecutive rows; lane owns cols [4*lane, 4*lane+4).
    const int row0 = (bid & 3) * 32 + warp * 4;
    const int c0   = lane * 4;

    // Per-row 4-bit membership masks (bit k = col c0+k inside any rect)
    unsigned m0 = 0u, m1 = 0u, m2 = 0u, m3 = 0u;
#pragma unroll
    for (int j = 0; j < BM_NBLK; j++) {
        int tj = __shfl_sync(0xFFFFFFFFu, top,   j);
        int bj = __shfl_sync(0xFFFFFFFFu, bot,   j);
        int lj = __shfl_sync(0xFFFFFFFFu, left,  j);
        int rj = __shfl_sync(0xFFFFFFFFu, right, j);
        int lo = max(lj - c0, 0);
        int hi = min(rj - c0, 4);
        unsigned cm = (hi > lo) ? (((1u << hi) - 1u) & ~((1u << lo) - 1u)) : 0u;
        if ((row0 + 0 >= tj) & (row0 + 0 < bj)) m0 |= cm;
        if ((row0 + 1 >= tj) & (row0 + 1 < bj)) m1 |= cm;
        if ((row0 + 2 >= tj) & (row0 + 2 < bj)) m2 |= cm;
        if ((row0 + 3 >= tj) & (row0 + 3 < bj)) m3 |= cm;
    }

    const unsigned ONE = 0x3F800000u;  // 1.0f
    uint4 t[4], c[4];
    unsigned mm[4] = {m0, m1, m2, m3};
#pragma unroll
    for (int r = 0; r < 4; r++) {
        t[r].x = (mm[r] & 1u) ? ONE : 0u;
        t[r].y = (mm[r] & 2u) ? ONE : 0u;
        t[r].z = (mm[r] & 4u) ? ONE : 0u;
        t[r].w = (mm[r] & 8u) ? ONE : 0u;
        c[r].x = t[r].x ^ ONE;
        c[r].y = t[r].y ^ ONE;
        c[r].z = t[r].z ^ ONE;
        c[r].w = t[r].w ^ ONE;
    }

    float* ctx = out;
    float* tgt = out + (size_t)BM_BATCH * BM_SEQ;
    // lane l writes 16B at row*512 + l*16 -> warp instruction = contiguous 512B
    const size_t base = (size_t)b * BM_SEQ + (size_t)row0 * BM_W + c0;

#pragma unroll
    for (int r = 0; r < 4; r++)
        *reinterpret_cast<uint4*>(tgt + base + (size_t)r * BM_W) = t[r];
#pragma unroll
    for (int r = 0; r < 4; r++)
        *reinterpret_cast<uint4*>(ctx + base + (size_t)r * BM_W) = c[r];
}

extern "C" void kernel_launch(void* const* d_in, const int* in_sizes, int n_in,
                              void* d_out, int out_size)
{
    const float* scales_u  = (const float*)d_in[0];
    const float* rand_top  = (const float*)d_in[1];
    const float* rand_left = (const float*)d_in[2];
    float* out = (float*)d_out;

    block_mask_kernel<<<BM_BATCH * 4, 256>>>(scales_u, rand_top, rand_left, out);
}